// round 7
// baseline (speedup 1.0000x reference)
#include <cuda_runtime.h>
#include <cuda_bf16.h>
#include <cstdint>

// ---------------- problem constants ----------------
#define B_   1024
#define S_   336
#define C_   64
#define O_   168
#define T_   96
#define O2   192            // K padded to 3 chunks of 64
#define CH   64             // k per chunk
#define NCH  3
#define MT   256            // batches per GEMM CTA

// ---------------- scratch (device globals; no allocs) ----------------
__device__ __nv_bfloat16 g_xhi[(size_t)C_ * B_ * O2];       // [c][b][o]  (o padded w/ zeros)
__device__ __nv_bfloat16 g_xlo[(size_t)C_ * B_ * O2];
__device__ unsigned char g_bhi[(size_t)C_ * NCH * T_ * 128];// pre-swizzled W hi image
__device__ unsigned char g_blo[(size_t)C_ * NCH * T_ * 128];
__device__ float         g_yT [(size_t)C_ * B_ * T_];       // [c][b][t]

// split f into bf16 hi + bf16 lo (pairwise, packed)
__device__ __forceinline__ void split2(float f0, float f1, uint32_t& h, uint32_t& l)
{
    __nv_bfloat162 hb = __floats2bfloat162_rn(f0, f1);
    float r0 = f0 - __bfloat162float(hb.x);
    float r1 = f1 - __bfloat162float(hb.y);
    __nv_bfloat162 lb = __floats2bfloat162_rn(r0, r1);
    h = *reinterpret_cast<uint32_t*>(&hb);
    l = *reinterpret_cast<uint32_t*>(&lb);
}
__device__ __forceinline__ uint32_t smem_u32(const void* p) {
    uint32_t a;
    asm("{ .reg .u64 t; cvta.to.shared.u64 t, %1; cvt.u32.u64 %0, t; }" : "=r"(a) : "l"(p));
    return a;
}
__device__ __forceinline__ void mma16816(float* d, const uint32_t* a, const uint32_t* b)
{
    asm volatile(
        "mma.sync.aligned.m16n8k16.row.col.f32.bf16.bf16.f32 "
        "{%0,%1,%2,%3}, {%4,%5,%6,%7}, {%8,%9}, {%0,%1,%2,%3};"
        : "+f"(d[0]), "+f"(d[1]), "+f"(d[2]), "+f"(d[3])
        : "r"(a[0]), "r"(a[1]), "r"(a[2]), "r"(a[3]), "r"(b[0]), "r"(b[1]));
}
__device__ __forceinline__ void ldsm4(uint32_t* r, uint32_t addr)
{
    asm volatile("ldmatrix.sync.aligned.m8n8.x4.shared.b16 {%0,%1,%2,%3}, [%4];"
                 : "=r"(r[0]), "=r"(r[1]), "=r"(r[2]), "=r"(r[3]) : "r"(addr));
}
#define CPA16(dst, src) \
    asm volatile("cp.async.cg.shared.global [%0], [%1], 16;" :: "r"(dst), "l"(src))
#define CPA_COMMIT() asm volatile("cp.async.commit_group;" ::: "memory")
#define CPA_WAIT(n)  asm volatile("cp.async.wait_group %0;" :: "n"(n) : "memory")

// ================= T0: W[c][o][t] -> pre-swizzled bf16 hi/lo images =================
__global__ __launch_bounds__(256)
void t0_kernel(const float* __restrict__ W)
{
    const int c = blockIdx.x;
    const float* Wc = W + (size_t)c * (O_ * T_);
    for (int idx = threadIdx.x; idx < 48 * T_; idx += 256) {
        int oq = idx / T_;
        int t  = idx - oq * T_;
        int o  = oq * 4;
        float f0 = (o + 0 < O_) ? Wc[(o + 0) * T_ + t] : 0.f;
        float f1 = (o + 1 < O_) ? Wc[(o + 1) * T_ + t] : 0.f;
        float f2 = (o + 2 < O_) ? Wc[(o + 2) * T_ + t] : 0.f;
        float f3 = (o + 3 < O_) ? Wc[(o + 3) * T_ + t] : 0.f;
        uint2 hv, lv;
        split2(f0, f1, hv.x, lv.x);
        split2(f2, f3, hv.y, lv.y);
        int chunk = o >> 6;
        int kc    = o & 63;
        uint32_t off = (((uint32_t)(c * NCH + chunk) * T_ + t) << 7)
                     + (((uint32_t)(kc >> 3) ^ (t & 7)) << 4) + ((kc >> 2) & 1) * 8;
        *(uint2*)(g_bhi + off) = hv;
        *(uint2*)(g_blo + off) = lv;
    }
}

// ================= T1: x[B,S,C] -> xT hi/lo [C,B,O2] (zero-padded K) =================
__global__ __launch_bounds__(256)
void t1_kernel(const float* __restrict__ x)
{
    __shared__ float smt[32 * 172];
    const int b    = blockIdx.x;
    const int half = blockIdx.y;
    const uint4* xb = reinterpret_cast<const uint4*>(
        x + (size_t)b * (S_ * C_) + (size_t)(S_ - O_) * C_);

    for (int i = threadIdx.x; i < O_ * 8; i += 256) {
        int o = i >> 3, q = i & 7;
        uint4 v = xb[o * 16 + half * 8 + q];
        float* d = &smt[(q * 4) * 172 + o];
        d[0 * 172] = __uint_as_float(v.x);
        d[1 * 172] = __uint_as_float(v.y);
        d[2 * 172] = __uint_as_float(v.z);
        d[3 * 172] = __uint_as_float(v.w);
    }
    __syncthreads();

    for (int idx = threadIdx.x; idx < 32 * 24; idx += 256) {
        int cl = idx / 24, ch = idx - cl * 24;
        uint4 hw = make_uint4(0, 0, 0, 0), lw = make_uint4(0, 0, 0, 0);
        if (ch < 21) {
            const float* src = &smt[cl * 172 + ch * 8];
            float4 f0 = *(const float4*)(src);
            float4 f1 = *(const float4*)(src + 4);
            split2(f0.x, f0.y, hw.x, lw.x);
            split2(f0.z, f0.w, hw.y, lw.y);
            split2(f1.x, f1.y, hw.z, lw.z);
            split2(f1.z, f1.w, hw.w, lw.w);
        }
        size_t base = ((size_t)(half * 32 + cl) * B_ + b) * O2 + ch * 8;
        *(uint4*)(g_xhi + base) = hw;
        *(uint4*)(g_xlo + base) = lw;
    }
}

// ================= GEMM: MT=256, 8 warps (4m x 2n), warp tile 64x48 =================
// stage layout (bytes): A_hi 32K | A_lo 32K | B_hi 12K | B_lo 12K = 88K; 2 stages = 176K
#define OFF_AHI  0
#define OFF_ALO  32768
#define OFF_BHI  65536
#define OFF_BLO  77824
#define STG      90112
#define SMEM_TOT (2 * STG)

__device__ __forceinline__ void fill_chunk(uint32_t sbase, int c, int b0, int chunk, int tid)
{
    const char* axh = (const char*)g_xhi
        + ((size_t)((c << 10) + b0) * O2 + (size_t)chunk * CH) * 2;
    const char* axl = (const char*)g_xlo
        + ((size_t)((c << 10) + b0) * O2 + (size_t)chunk * CH) * 2;
    #pragma unroll
    for (int it = 0; it < 8; it++) {
        int i = tid + it * 256;
        int r = i >> 3, cq = i & 7;
        uint32_t sw = (uint32_t)r * 128 + (((uint32_t)cq ^ (r & 7)) << 4);
        CPA16(sbase + OFF_AHI + sw, axh + (size_t)r * (O2 * 2) + cq * 16);
        CPA16(sbase + OFF_ALO + sw, axl + (size_t)r * (O2 * 2) + cq * 16);
    }
    const char* bh = (const char*)g_bhi + (size_t)(c * NCH + chunk) * (T_ * 128);
    const char* bl = (const char*)g_blo + (size_t)(c * NCH + chunk) * (T_ * 128);
    #pragma unroll
    for (int it = 0; it < 3; it++) {
        int i = tid + it * 256;
        CPA16(sbase + OFF_BHI + i * 16, bh + (size_t)i * 16);
        CPA16(sbase + OFF_BLO + i * 16, bl + (size_t)i * 16);
    }
}

__device__ __forceinline__ void mma_chunk(uint32_t base, int wm, int wn, int lane,
                                          float (*acc)[6][4])
{
    const int l7   = lane & 7;
    const int hi16 = lane >> 4;
    const int cbit = (lane >> 3) & 1;
    const int rA0  = wm * 64 + (lane & 15);
    const int tl   = l7 + (hi16 << 3);

    #pragma unroll
    for (int ks = 0; ks < 4; ks++) {
        uint32_t ah[4][4], al[4][4], bh[3][4], bl[3][4];
        const int kqa = ks * 2 + hi16;
        uint32_t sa = base + OFF_AHI + (uint32_t)rA0 * 128 + (((uint32_t)(kqa ^ l7)) << 4);
        #pragma unroll
        for (int mi = 0; mi < 4; mi++) {
            ldsm4(ah[mi], sa + mi * (16 * 128));
            ldsm4(al[mi], sa + mi * (16 * 128) + (OFF_ALO - OFF_AHI));
        }
        const int kqb = ks * 2 + cbit;
        #pragma unroll
        for (int j = 0; j < 3; j++) {
            int t = wn * 48 + j * 16 + tl;
            uint32_t sbb = base + OFF_BHI + (uint32_t)t * 128 + (((uint32_t)(kqb ^ l7)) << 4);
            ldsm4(bh[j], sbb);
            ldsm4(bl[j], sbb + (OFF_BLO - OFF_BHI));
        }
        #pragma unroll
        for (int j = 0; j < 3; j++)
            #pragma unroll
            for (int h = 0; h < 2; h++) {
                const uint32_t* bhf = &bh[j][2 * h];
                const uint32_t* blf = &bl[j][2 * h];
                #pragma unroll
                for (int mi = 0; mi < 4; mi++) {
                    mma16816(acc[mi][2 * j + h], ah[mi], bhf);   // hi*hi
                    mma16816(acc[mi][2 * j + h], ah[mi], blf);   // hi*lo
                    mma16816(acc[mi][2 * j + h], al[mi], bhf);   // lo*hi
                }
            }
    }
}

__global__ __launch_bounds__(256, 1)
void gemm_kernel(const float* __restrict__ bias)
{
    extern __shared__ char smem[];
    const uint32_t sb = smem_u32(smem);
    const int c    = blockIdx.x;
    const int b0   = blockIdx.y * MT;
    const int tid  = threadIdx.x;
    const int lane = tid & 31;
    const int wid  = tid >> 5;
    const int wm   = wid & 3;
    const int wn   = wid >> 2;
    const int grp  = lane >> 2;
    const int qid  = lane & 3;

    float acc[4][6][4];
    #pragma unroll
    for (int mi = 0; mi < 4; mi++)
        #pragma unroll
        for (int ni = 0; ni < 6; ni++)
            #pragma unroll
            for (int r = 0; r < 4; r++)
                acc[mi][ni][r] = 0.f;

    // ---- software pipeline: 3 chunks, 2 stages ----
    fill_chunk(sb,        c, b0, 0, tid); CPA_COMMIT();
    fill_chunk(sb + STG,  c, b0, 1, tid); CPA_COMMIT();
    CPA_WAIT(1);
    __syncthreads();
    mma_chunk(sb, wm, wn, lane, acc);            // chunk 0
    __syncthreads();
    fill_chunk(sb,        c, b0, 2, tid); CPA_COMMIT();
    CPA_WAIT(1);
    __syncthreads();
    mma_chunk(sb + STG, wm, wn, lane, acc);      // chunk 1
    CPA_WAIT(0);
    __syncthreads();
    mma_chunk(sb, wm, wn, lane, acc);            // chunk 2

    // ---- epilogue: bias + store yT[c][b][t] ----
    const float* bc = bias + c * T_;
    #pragma unroll
    for (int mi = 0; mi < 4; mi++) {
        const int b = b0 + wm * 64 + mi * 16 + grp;
        float* y0 = g_yT + ((size_t)c * B_ + b) * T_;
        float* y1 = y0 + 8 * T_;
        #pragma unroll
        for (int ni = 0; ni < 6; ni++) {
            const int t = wn * 48 + ni * 8 + qid * 2;
            const float bv0 = __ldg(bc + t);
            const float bv1 = __ldg(bc + t + 1);
            float2 v0 = { acc[mi][ni][0] + bv0, acc[mi][ni][1] + bv1 };
            float2 v1 = { acc[mi][ni][2] + bv0, acc[mi][ni][3] + bv1 };
            *(float2*)(y0 + t) = v0;
            *(float2*)(y1 + t) = v1;
        }
    }
}

// ================= T2: yT[C, B*T] -> out[B*T, C], 64 x 128 tiles =================
__global__ __launch_bounds__(256)
void t2_kernel(float* __restrict__ out)
{
    __shared__ float tile[64 * 132];              // pitch 132
    const int bt0 = blockIdx.x * 128;

    #pragma unroll
    for (int it = 0; it < 8; it++) {
        int i = threadIdx.x + it * 256;           // 2048 float4 loads
        int cc = i >> 5, q = i & 31;
        float4 v = *(const float4*)&g_yT[(size_t)cc * (B_ * T_) + bt0 + q * 4];
        *(float4*)&tile[cc * 132 + q * 4] = v;
    }
    __syncthreads();
    #pragma unroll
    for (int it = 0; it < 8; it++) {
        int i = threadIdx.x + it * 256;
        int r = i >> 4, cq = i & 15;
        float4 v;
        v.x = tile[(cq * 4 + 0) * 132 + r];
        v.y = tile[(cq * 4 + 1) * 132 + r];
        v.z = tile[(cq * 4 + 2) * 132 + r];
        v.w = tile[(cq * 4 + 3) * 132 + r];
        *(float4*)&out[(size_t)(bt0 + r) * C_ + cq * 4] = v;
    }
}

// ================= launch =================
extern "C" void kernel_launch(void* const* d_in, const int* in_sizes, int n_in,
                              void* d_out, int out_size)
{
    const float* x    = (const float*)d_in[0];  // [B, S, C]
    const float* W    = (const float*)d_in[1];  // [C, O, T]
    const float* bias = (const float*)d_in[2];  // [C, T]
    float* out = (float*)d_out;                 // [B, T, C]

    cudaFuncSetAttribute(gemm_kernel,
                         cudaFuncAttributeMaxDynamicSharedMemorySize, SMEM_TOT);

    t0_kernel<<<C_, 256>>>(W);
    t1_kernel<<<dim3(B_, 2), 256>>>(x);
    gemm_kernel<<<dim3(C_, B_ / MT), 256, SMEM_TOT>>>(bias);
    t2_kernel<<<(B_ * T_) / 128, 256>>>(out);
}

// round 8
// speedup vs baseline: 1.1370x; 1.1370x over previous
#include <cuda_runtime.h>
#include <cuda_bf16.h>
#include <cstdint>

// ---------------- problem constants ----------------
#define B_   1024
#define S_   336
#define C_   64
#define O_   168
#define T_   96
#define O2   192            // K padded to 3 chunks of 64
#define CH   64             // k per chunk
#define NCH  3
#define MT   128            // batches per GEMM CTA

// ---------------- scratch (device globals; no allocs) ----------------
__device__ __nv_bfloat16 g_xhi[(size_t)C_ * B_ * O2];       // [c][b][o]  (o padded w/ zeros)
__device__ __nv_bfloat16 g_xlo[(size_t)C_ * B_ * O2];
__device__ unsigned char g_bhi[(size_t)C_ * NCH * T_ * 128];// pre-swizzled W hi image
__device__ unsigned char g_blo[(size_t)C_ * NCH * T_ * 128];
__device__ float         g_yT [(size_t)C_ * B_ * T_];       // [c][b][t]

// split f into bf16 hi + bf16 lo (pairwise, packed)
__device__ __forceinline__ void split2(float f0, float f1, uint32_t& h, uint32_t& l)
{
    __nv_bfloat162 hb = __floats2bfloat162_rn(f0, f1);
    float r0 = f0 - __bfloat162float(hb.x);
    float r1 = f1 - __bfloat162float(hb.y);
    __nv_bfloat162 lb = __floats2bfloat162_rn(r0, r1);
    h = *reinterpret_cast<uint32_t*>(&hb);
    l = *reinterpret_cast<uint32_t*>(&lb);
}
__device__ __forceinline__ uint32_t smem_u32(const void* p) {
    uint32_t a;
    asm("{ .reg .u64 t; cvta.to.shared.u64 t, %1; cvt.u32.u64 %0, t; }" : "=r"(a) : "l"(p));
    return a;
}
__device__ __forceinline__ void mma16816(float* d, const uint32_t* a, const uint32_t* b)
{
    asm volatile(
        "mma.sync.aligned.m16n8k16.row.col.f32.bf16.bf16.f32 "
        "{%0,%1,%2,%3}, {%4,%5,%6,%7}, {%8,%9}, {%0,%1,%2,%3};"
        : "+f"(d[0]), "+f"(d[1]), "+f"(d[2]), "+f"(d[3])
        : "r"(a[0]), "r"(a[1]), "r"(a[2]), "r"(a[3]), "r"(b[0]), "r"(b[1]));
}
__device__ __forceinline__ void ldsm4(uint32_t* r, uint32_t addr)
{
    asm volatile("ldmatrix.sync.aligned.m8n8.x4.shared.b16 {%0,%1,%2,%3}, [%4];"
                 : "=r"(r[0]), "=r"(r[1]), "=r"(r[2]), "=r"(r[3]) : "r"(addr));
}
#define CPA16(dst, src) \
    asm volatile("cp.async.cg.shared.global [%0], [%1], 16;" :: "r"(dst), "l"(src))
#define CPA_COMMIT() asm volatile("cp.async.commit_group;" ::: "memory")
#define CPA_WAIT(n)  asm volatile("cp.async.wait_group %0;" :: "n"(n) : "memory")

// ================= T01 fused: y<2 -> x transpose/split halves; y==2 -> W images =================
__global__ __launch_bounds__(256)
void t01_kernel(const float* __restrict__ x, const float* __restrict__ W)
{
    if (blockIdx.y == 2) {
        // ---- t0 body: W[c][o][t] -> pre-swizzled bf16 hi/lo images ----
        if (blockIdx.x >= C_) return;
        const int c = blockIdx.x;
        const float* Wc = W + (size_t)c * (O_ * T_);
        for (int idx = threadIdx.x; idx < 48 * T_; idx += 256) {
            int oq = idx / T_;
            int t  = idx - oq * T_;
            int o  = oq * 4;
            float f0 = (o + 0 < O_) ? Wc[(o + 0) * T_ + t] : 0.f;
            float f1 = (o + 1 < O_) ? Wc[(o + 1) * T_ + t] : 0.f;
            float f2 = (o + 2 < O_) ? Wc[(o + 2) * T_ + t] : 0.f;
            float f3 = (o + 3 < O_) ? Wc[(o + 3) * T_ + t] : 0.f;
            uint2 hv, lv;
            split2(f0, f1, hv.x, lv.x);
            split2(f2, f3, hv.y, lv.y);
            int chunk = o >> 6;
            int kc    = o & 63;
            uint32_t off = (((uint32_t)(c * NCH + chunk) * T_ + t) << 7)
                         + (((uint32_t)(kc >> 3) ^ (t & 7)) << 4) + ((kc >> 2) & 1) * 8;
            *(uint2*)(g_bhi + off) = hv;
            *(uint2*)(g_blo + off) = lv;
        }
        return;
    }

    // ---- t1 body: x[B,S,C] -> xT hi/lo [C,B,O2], one 32-channel half ----
    __shared__ float smt[32 * 172];
    const int b    = blockIdx.x;
    const int half = blockIdx.y;
    const uint4* xb = reinterpret_cast<const uint4*>(
        x + (size_t)b * (S_ * C_) + (size_t)(S_ - O_) * C_);

    // batch all global loads into registers first (ILP), then STS
    uint4 v[6];
    #pragma unroll
    for (int it = 0; it < 6; it++) {
        int i = threadIdx.x + it * 256;
        if (i < O_ * 8) {
            int o = i >> 3, q = i & 7;
            v[it] = xb[o * 16 + half * 8 + q];
        }
    }
    #pragma unroll
    for (int it = 0; it < 6; it++) {
        int i = threadIdx.x + it * 256;
        if (i < O_ * 8) {
            int o = i >> 3, q = i & 7;
            float* d = &smt[(q * 4) * 172 + o];
            d[0 * 172] = __uint_as_float(v[it].x);
            d[1 * 172] = __uint_as_float(v[it].y);
            d[2 * 172] = __uint_as_float(v[it].z);
            d[3 * 172] = __uint_as_float(v[it].w);
        }
    }
    __syncthreads();

    for (int idx = threadIdx.x; idx < 32 * 24; idx += 256) {
        int cl = idx / 24, ch = idx - cl * 24;
        uint4 hw = make_uint4(0, 0, 0, 0), lw = make_uint4(0, 0, 0, 0);
        if (ch < 21) {
            const float* src = &smt[cl * 172 + ch * 8];
            float4 f0 = *(const float4*)(src);
            float4 f1 = *(const float4*)(src + 4);
            split2(f0.x, f0.y, hw.x, lw.x);
            split2(f0.z, f0.w, hw.y, lw.y);
            split2(f1.x, f1.y, hw.z, lw.z);
            split2(f1.z, f1.w, hw.w, lw.w);
        }
        size_t base = ((size_t)(half * 32 + cl) * B_ + b) * O2 + ch * 8;
        *(uint4*)(g_xhi + base) = hw;
        *(uint4*)(g_xlo + base) = lw;
    }
}

// ================= GEMM: cp.async double-buffered, 3 k-chunks, 2 CTAs/SM (R6 config) =================
// stage layout (bytes): A_hi 16K | A_lo 16K | B_hi 12K | B_lo 12K  = 56K; 2 stages = 112K
#define OFF_AHI  0
#define OFF_ALO  16384
#define OFF_BHI  32768
#define OFF_BLO  45056
#define STG      57344
#define SMEM_TOT (2 * STG)

__device__ __forceinline__ void fill_chunk(uint32_t sbase, int c, int b0, int chunk, int tid)
{
    const char* axh = (const char*)g_xhi
        + ((size_t)((c << 10) + b0) * O2 + (size_t)chunk * CH) * 2;
    const char* axl = (const char*)g_xlo
        + ((size_t)((c << 10) + b0) * O2 + (size_t)chunk * CH) * 2;
    #pragma unroll
    for (int it = 0; it < 4; it++) {
        int i = tid + it * 256;
        int r = i >> 3, cq = i & 7;
        uint32_t sw = (uint32_t)r * 128 + (((uint32_t)cq ^ (r & 7)) << 4);
        CPA16(sbase + OFF_AHI + sw, axh + (size_t)r * (O2 * 2) + cq * 16);
        CPA16(sbase + OFF_ALO + sw, axl + (size_t)r * (O2 * 2) + cq * 16);
    }
    const char* bh = (const char*)g_bhi + (size_t)(c * NCH + chunk) * (T_ * 128);
    const char* bl = (const char*)g_blo + (size_t)(c * NCH + chunk) * (T_ * 128);
    #pragma unroll
    for (int it = 0; it < 3; it++) {
        int i = tid + it * 256;
        CPA16(sbase + OFF_BHI + i * 16, bh + (size_t)i * 16);
        CPA16(sbase + OFF_BLO + i * 16, bl + (size_t)i * 16);
    }
}

__device__ __forceinline__ void mma_chunk(uint32_t base, int wm, int wn, int lane,
                                          float (*acc)[6][4])
{
    const int l7   = lane & 7;
    const int hi16 = lane >> 4;
    const int cbit = (lane >> 3) & 1;
    const int rA0  = wm * 32 + (lane & 15);
    const int tl   = l7 + (hi16 << 3);

    #pragma unroll
    for (int ks = 0; ks < 4; ks++) {
        uint32_t ah[2][4], al[2][4], bh[3][4], bl[3][4];
        const int kqa = ks * 2 + hi16;
        uint32_t sa = base + OFF_AHI + (uint32_t)rA0 * 128 + (((uint32_t)(kqa ^ l7)) << 4);
        ldsm4(ah[0], sa);
        ldsm4(ah[1], sa + 16 * 128);
        uint32_t sl = sa + (OFF_ALO - OFF_AHI);
        ldsm4(al[0], sl);
        ldsm4(al[1], sl + 16 * 128);
        const int kqb = ks * 2 + cbit;
        #pragma unroll
        for (int j = 0; j < 3; j++) {
            int t = wn * 48 + j * 16 + tl;
            uint32_t sbb = base + OFF_BHI + (uint32_t)t * 128 + (((uint32_t)(kqb ^ l7)) << 4);
            ldsm4(bh[j], sbb);
            ldsm4(bl[j], sbb + (OFF_BLO - OFF_BHI));
        }
        #pragma unroll
        for (int j = 0; j < 3; j++)
            #pragma unroll
            for (int h = 0; h < 2; h++) {
                const uint32_t* bhf = &bh[j][2 * h];
                const uint32_t* blf = &bl[j][2 * h];
                #pragma unroll
                for (int mi = 0; mi < 2; mi++) {
                    mma16816(acc[mi][2 * j + h], ah[mi], bhf);   // hi*hi
                    mma16816(acc[mi][2 * j + h], ah[mi], blf);   // hi*lo
                    mma16816(acc[mi][2 * j + h], al[mi], bhf);   // lo*hi
                }
            }
    }
}

__global__ __launch_bounds__(256, 2)
void gemm_kernel(const float* __restrict__ bias)
{
    extern __shared__ char smem[];
    const uint32_t sb = smem_u32(smem);
    const int c    = blockIdx.x;
    const int b0   = blockIdx.y * MT;
    const int tid  = threadIdx.x;
    const int lane = tid & 31;
    const int wid  = tid >> 5;
    const int wm   = wid & 3;
    const int wn   = wid >> 2;
    const int grp  = lane >> 2;
    const int qid  = lane & 3;

    float acc[2][6][4];
    #pragma unroll
    for (int mi = 0; mi < 2; mi++)
        #pragma unroll
        for (int ni = 0; ni < 6; ni++)
            #pragma unroll
            for (int r = 0; r < 4; r++)
                acc[mi][ni][r] = 0.f;

    // ---- software pipeline: 3 chunks, 2 stages ----
    fill_chunk(sb,        c, b0, 0, tid); CPA_COMMIT();
    fill_chunk(sb + STG,  c, b0, 1, tid); CPA_COMMIT();
    CPA_WAIT(1);
    __syncthreads();
    mma_chunk(sb, wm, wn, lane, acc);            // chunk 0
    __syncthreads();
    fill_chunk(sb,        c, b0, 2, tid); CPA_COMMIT();
    CPA_WAIT(1);
    __syncthreads();
    mma_chunk(sb + STG, wm, wn, lane, acc);      // chunk 1
    CPA_WAIT(0);
    __syncthreads();
    mma_chunk(sb, wm, wn, lane, acc);            // chunk 2

    // ---- epilogue: bias + store yT[c][b][t] ----
    const float* bc = bias + c * T_;
    #pragma unroll
    for (int mi = 0; mi < 2; mi++) {
        const int b = b0 + wm * 32 + mi * 16 + grp;
        float* y0 = g_yT + ((size_t)c * B_ + b) * T_;
        float* y1 = y0 + 8 * T_;
        #pragma unroll
        for (int ni = 0; ni < 6; ni++) {
            const int t = wn * 48 + ni * 8 + qid * 2;
            const float bv0 = __ldg(bc + t);
            const float bv1 = __ldg(bc + t + 1);
            float2 v0 = { acc[mi][ni][0] + bv0, acc[mi][ni][1] + bv1 };
            float2 v1 = { acc[mi][ni][2] + bv0, acc[mi][ni][3] + bv1 };
            *(float2*)(y0 + t) = v0;
            *(float2*)(y1 + t) = v1;
        }
    }
}

// ================= T2: yT[C, B*T] -> out[B*T, C], two 64x64 tiles per CTA =================
__global__ __launch_bounds__(256)
void t2_kernel(float* __restrict__ out)
{
    __shared__ float tile0[64 * 69];
    __shared__ float tile1[64 * 69];
    const int bt0 = blockIdx.x * 128;

    // 8 independent LDG.128 per thread, all in flight before any STS
    float4 va[4], vb[4];
    #pragma unroll
    for (int it = 0; it < 4; it++) {
        int i = threadIdx.x + it * 256;
        int cc = i >> 4, q = i & 15;
        const float* src = &g_yT[(size_t)cc * (B_ * T_) + bt0 + q * 4];
        va[it] = *(const float4*)(src);
        vb[it] = *(const float4*)(src + 64);
    }
    #pragma unroll
    for (int it = 0; it < 4; it++) {
        int i = threadIdx.x + it * 256;
        int cc = i >> 4, q = i & 15;
        float* d0 = &tile0[cc * 69 + q * 4];
        d0[0] = va[it].x; d0[1] = va[it].y; d0[2] = va[it].z; d0[3] = va[it].w;
        float* d1 = &tile1[cc * 69 + q * 4];
        d1[0] = vb[it].x; d1[1] = vb[it].y; d1[2] = vb[it].z; d1[3] = vb[it].w;
    }
    __syncthreads();
    #pragma unroll
    for (int it = 0; it < 4; it++) {
        int i = threadIdx.x + it * 256;
        int r = i >> 4, cq = i & 15;
        float4 v, w;
        v.x = tile0[(cq * 4 + 0) * 69 + r];
        v.y = tile0[(cq * 4 + 1) * 69 + r];
        v.z = tile0[(cq * 4 + 2) * 69 + r];
        v.w = tile0[(cq * 4 + 3) * 69 + r];
        w.x = tile1[(cq * 4 + 0) * 69 + r];
        w.y = tile1[(cq * 4 + 1) * 69 + r];
        w.z = tile1[(cq * 4 + 2) * 69 + r];
        w.w = tile1[(cq * 4 + 3) * 69 + r];
        *(float4*)&out[(size_t)(bt0 + r) * C_ + cq * 4] = v;
        *(float4*)&out[(size_t)(bt0 + 64 + r) * C_ + cq * 4] = w;
    }
}

// ================= launch =================
extern "C" void kernel_launch(void* const* d_in, const int* in_sizes, int n_in,
                              void* d_out, int out_size)
{
    const float* x    = (const float*)d_in[0];  // [B, S, C]
    const float* W    = (const float*)d_in[1];  // [C, O, T]
    const float* bias = (const float*)d_in[2];  // [C, T]
    float* out = (float*)d_out;                 // [B, T, C]

    cudaFuncSetAttribute(gemm_kernel,
                         cudaFuncAttributeMaxDynamicSharedMemorySize, SMEM_TOT);

    t01_kernel<<<dim3(B_, 3), 256>>>(x, W);
    gemm_kernel<<<dim3(C_, B_ / MT), 256, SMEM_TOT>>>(bias);
    t2_kernel<<<(B_ * T_) / 128, 256>>>(out);
}